// round 17
// baseline (speedup 1.0000x reference)
#include <cuda_runtime.h>
#include <cuda_bf16.h>
#include <cstdint>
#include <cstddef>

#define BB 8
#define SS 1024
#define DMM 1024
#define HH 16
#define DKK 64
#define DVV 64
#define MROWS (BB*SS)      /* 8192 */
#define NBH (BB*HH)        /* 128  */
#define APLANE ((size_t)MROWS*DMM)
#define WPLANE ((size_t)DMM*DMM)

// ---------------- scratch (static device globals; no runtime allocation) ----
__device__ float g_attn[(size_t)NBH*SS*SS];            // fallback attn buffer
__device__ __nv_bfloat16 g_Ahi[3*APLANE];
__device__ __nv_bfloat16 g_Alo[3*APLANE];
__device__ __nv_bfloat16 g_Bhi[4*WPLANE];
__device__ __nv_bfloat16 g_Blo[4*WPLANE];
__device__ __nv_bfloat16 g_Qb [APLANE];
__device__ __nv_bfloat16 g_Kb [APLANE];
__device__ __nv_bfloat16 g_Vhi[APLANE];
__device__ __nv_bfloat16 g_Vlo[APLANE];
__device__ __nv_bfloat16 g_AOhi[APLANE];
__device__ __nv_bfloat16 g_AOlo[APLANE];

// ============================================================================
// helpers (compute_80-level PTX only)
// ============================================================================
__device__ __forceinline__ uint32_t smem_u32(const void* p) {
    uint32_t a;
    asm("{ .reg .u64 t; cvta.to.shared.u64 t, %1; cvt.u32.u64 %0, t; }" : "=r"(a) : "l"(p));
    return a;
}
__device__ __forceinline__ void cp_async16(uint32_t dst, const void* src) {
    asm volatile("cp.async.cg.shared.global [%0], [%1], 16;" :: "r"(dst), "l"(src) : "memory");
}
__device__ __forceinline__ void ld4(uint32_t* r, uint32_t addr) {
    asm volatile("ldmatrix.sync.aligned.m8n8.x4.shared.b16 {%0,%1,%2,%3}, [%4];"
                 : "=r"(r[0]), "=r"(r[1]), "=r"(r[2]), "=r"(r[3]) : "r"(addr));
}
__device__ __forceinline__ void ld4t(uint32_t* r, uint32_t addr) {
    asm volatile("ldmatrix.sync.aligned.m8n8.x4.trans.shared.b16 {%0,%1,%2,%3}, [%4];"
                 : "=r"(r[0]), "=r"(r[1]), "=r"(r[2]), "=r"(r[3]) : "r"(addr));
}
__device__ __forceinline__ void mma16816(float* d, const uint32_t* a,
                                         uint32_t b0, uint32_t b1) {
    asm volatile(
        "mma.sync.aligned.m16n8k16.row.col.f32.bf16.bf16.f32 "
        "{%0,%1,%2,%3}, {%4,%5,%6,%7}, {%8,%9}, {%0,%1,%2,%3};"
        : "+f"(d[0]), "+f"(d[1]), "+f"(d[2]), "+f"(d[3])
        : "r"(a[0]), "r"(a[1]), "r"(a[2]), "r"(a[3]), "r"(b0), "r"(b1));
}
__device__ __forceinline__ uint32_t packbf2(__nv_bfloat16 x, __nv_bfloat16 y) {
    __nv_bfloat162 t; t.x = x; t.y = y;
    return *reinterpret_cast<uint32_t*>(&t);
}
__device__ __forceinline__ void packhl(float x, float y, uint32_t& h, uint32_t& l) {
    __nv_bfloat16 hx = __float2bfloat16(x), hy = __float2bfloat16(y);
    h = packbf2(hx, hy);
    l = packbf2(__float2bfloat16(x - __bfloat162float(hx)),
                __float2bfloat16(y - __bfloat162float(hy)));
}

// ============================================================================
// batched bf16x[nseg] mma.sync GEMM: C[z] = A[z] @ W[z] + bias[z].
// nseg=3: hi*hi + lo*hi + hi*lo.  nseg=2: + lo*hi.  nseg=1: hi*hi only.
// BK=64, 2-stage, 128x128 CTA tile. launch_bounds(256,2).
// ============================================================================
#define GS_STRIDE 144                 /* bytes per smem row (72 bf16) */
#define G_STAGE (128*GS_STRIDE)       /* 18432 */
#define G_SMEM  (4*G_STAGE)           /* 73728 */

struct G3B {
    const __nv_bfloat16* Ahi[3];
    const __nv_bfloat16* Alo[3];
    const __nv_bfloat16* Bhi[3];
    const __nv_bfloat16* Blo[3];
    const float* bias[3];
    float* C[3];
    __nv_bfloat16* Chi[3];
    __nv_bfloat16* Clo[3];
    int nseg[3];
};

__global__ __launch_bounds__(256, 2)
void gemm3x(G3B bat, int M, int N, int K)
{
    extern __shared__ char gsm[];
    const uint32_t sa0 = smem_u32(gsm);
    const uint32_t sb0 = sa0 + 2 * G_STAGE;
    const int z = blockIdx.z;

    const __nv_bfloat16* Ahi = bat.Ahi[z];
    const __nv_bfloat16* Alo = bat.Alo[z];
    const __nv_bfloat16* Bhi = bat.Bhi[z];
    const __nv_bfloat16* Blo = bat.Blo[z];
    const float* bias = bat.bias[z];
    float* C = bat.C[z];
    __nv_bfloat16* Chi = bat.Chi[z];
    __nv_bfloat16* Clo = bat.Clo[z];

    const int tid = threadIdx.x, wid = tid >> 5, lane = tid & 31;
    const int warp_m = wid & 3, warp_n = wid >> 2;
    const int mbase = blockIdx.y * 128, nbase = blockIdx.x * 128;
    const int g = lane >> 3, lr = lane & 7;

    const int KC = K / 64;
    const int NC = bat.nseg[z] * KC;
    const __nv_bfloat16* Aseg[3] = { Ahi, Alo, Ahi };
    const __nv_bfloat16* Bseg[3] = { Bhi, Bhi, Blo };

    float acc[2][8][4];
#pragma unroll
    for (int i = 0; i < 2; i++)
#pragma unroll
        for (int j = 0; j < 8; j++)
#pragma unroll
            for (int v = 0; v < 4; v++) acc[i][j][v] = 0.f;

    auto issue = [&](int ch) {
        const int seg = ch / KC, k0 = (ch % KC) * 64, s = ch & 1;
        const __nv_bfloat16* Ap = Aseg[seg] + (size_t)mbase * K + k0;
        const __nv_bfloat16* Bp = Bseg[seg] + (size_t)nbase * K + k0;
#pragma unroll
        for (int i = 0; i < 4; i++) {
            int idx = tid + i * 256;
            int r = idx >> 3, cb = (idx & 7) * 16;
            cp_async16(sa0 + s * G_STAGE + r * GS_STRIDE + cb,
                       (const char*)(Ap + (size_t)r * K) + cb);
            cp_async16(sb0 + s * G_STAGE + r * GS_STRIDE + cb,
                       (const char*)(Bp + (size_t)r * K) + cb);
        }
        asm volatile("cp.async.commit_group;" ::: "memory");
    };

    issue(0);
    for (int c = 0; c < NC; c++) {
        const int s = c & 1;
        if (c + 1 < NC) {
            issue(c + 1);
            asm volatile("cp.async.wait_group 1;" ::: "memory");
        } else {
            asm volatile("cp.async.wait_group 0;" ::: "memory");
        }
        __syncthreads();

        const uint32_t ab = sa0 + s * G_STAGE;
        const uint32_t bb = sb0 + s * G_STAGE;
#pragma unroll
        for (int kk = 0; kk < 4; kk++) {
            const uint32_t colb = kk * 32 + ((g >> 1) << 4);
            uint32_t afr[2][4];
#pragma unroll
            for (int i = 0; i < 2; i++) {
                int row = warp_m * 32 + i * 16 + ((g & 1) << 3) + lr;
                ld4(afr[i], ab + row * GS_STRIDE + colb);
            }
#pragma unroll
            for (int j = 0; j < 4; j++) {
                uint32_t bfr[4];
                int row = warp_n * 64 + j * 16 + ((g & 1) << 3) + lr;
                ld4(bfr, bb + row * GS_STRIDE + colb);
#pragma unroll
                for (int i = 0; i < 2; i++) {
                    mma16816(acc[i][2 * j + 0], afr[i], bfr[0], bfr[2]);
                    mma16816(acc[i][2 * j + 1], afr[i], bfr[1], bfr[3]);
                }
            }
        }
        __syncthreads();
    }

    // epilogue
#pragma unroll
    for (int i = 0; i < 2; i++) {
        int row0 = mbase + warp_m * 32 + i * 16 + (lane >> 2);
#pragma unroll
        for (int j = 0; j < 8; j++) {
            int col = nbase + warp_n * 64 + j * 8 + (lane & 3) * 2;
            float b0 = __ldg(bias + col), b1 = __ldg(bias + col + 1);
            float v0 = acc[i][j][0] + b0, v1 = acc[i][j][1] + b1;
            float v2 = acc[i][j][2] + b0, v3 = acc[i][j][3] + b1;
            if (C) {
                *(float2*)(C + (size_t)row0 * N + col) = make_float2(v0, v1);
                *(float2*)(C + (size_t)(row0 + 8) * N + col) = make_float2(v2, v3);
            }
            if (Chi) {
                __nv_bfloat16 h0 = __float2bfloat16(v0), h1 = __float2bfloat16(v1);
                __nv_bfloat16 h2 = __float2bfloat16(v2), h3 = __float2bfloat16(v3);
                *(uint32_t*)(Chi + (size_t)row0 * N + col) = packbf2(h0, h1);
                *(uint32_t*)(Chi + (size_t)(row0 + 8) * N + col) = packbf2(h2, h3);
                if (Clo) {
                    *(uint32_t*)(Clo + (size_t)row0 * N + col) =
                        packbf2(__float2bfloat16(v0 - __bfloat162float(h0)),
                                __float2bfloat16(v1 - __bfloat162float(h1)));
                    *(uint32_t*)(Clo + (size_t)(row0 + 8) * N + col) =
                        packbf2(__float2bfloat16(v2 - __bfloat162float(h2)),
                                __float2bfloat16(v3 - __bfloat162float(h3)));
                }
            }
        }
    }
}

// ---------------------------------------------------------------------------
__global__ __launch_bounds__(256)
void asplit3(const float* __restrict__ q, const float* __restrict__ k,
             const float* __restrict__ v,
             __nv_bfloat16* __restrict__ hi0, __nv_bfloat16* __restrict__ lo0)
{
    const int p = blockIdx.y;
    const float* A = (p == 0) ? q : (p == 1) ? k : v;
    __nv_bfloat16* hi = hi0 + (size_t)p * APLANE;
    __nv_bfloat16* lo = lo0 + (size_t)p * APLANE;
    int i = blockIdx.x * 256 + threadIdx.x;
    float4 val = ((const float4*)A)[i];
    __nv_bfloat16 h0 = __float2bfloat16(val.x), h1 = __float2bfloat16(val.y);
    __nv_bfloat16 h2 = __float2bfloat16(val.z), h3 = __float2bfloat16(val.w);
    __nv_bfloat162* hp = (__nv_bfloat162*)hi;
    __nv_bfloat162* lp = (__nv_bfloat162*)lo;
    hp[2 * i + 0] = __nv_bfloat162(h0, h1);
    hp[2 * i + 1] = __nv_bfloat162(h2, h3);
    lp[2 * i + 0] = __nv_bfloat162(__float2bfloat16(val.x - __bfloat162float(h0)),
                                   __float2bfloat16(val.y - __bfloat162float(h1)));
    lp[2 * i + 1] = __nv_bfloat162(__float2bfloat16(val.z - __bfloat162float(h2)),
                                   __float2bfloat16(val.w - __bfloat162float(h3)));
}

// ---------------------------------------------------------------------------
struct W4 { const float* W[4]; };

__global__ __launch_bounds__(256)
void wsplit(W4 ws, __nv_bfloat16* __restrict__ thi0, __nv_bfloat16* __restrict__ tlo0)
{
    __shared__ float t[32][33];
    const int z = blockIdx.z;
    const float* W = ws.W[z];
    __nv_bfloat16* thi = thi0 + (size_t)z * WPLANE;
    __nv_bfloat16* tlo = tlo0 + (size_t)z * WPLANE;
    const int n0 = blockIdx.x * 32, k0 = blockIdx.y * 32;
    const int x = threadIdx.x & 31, y = (threadIdx.x >> 5);
#pragma unroll
    for (int j = 0; j < 32; j += 8)
        t[y + j][x] = W[(size_t)(k0 + y + j) * DMM + n0 + x];
    __syncthreads();
#pragma unroll
    for (int j = 0; j < 32; j += 8) {
        float v = t[x][y + j];
        __nv_bfloat16 h = __float2bfloat16(v);
        size_t o = (size_t)(n0 + y + j) * DMM + k0 + x;
        thi[o] = h;
        tlo[o] = __float2bfloat16(v - __bfloat162float(h));
    }
}

// ============================================================================
// Fused attention (identical to round-13 passing version): 512 threads,
// 16 warps (8 m x 2 n), 2-pass normalized, ballot-cached mask.
// ============================================================================
#define FA_STRIDE 144
#define OFF_Q  0
#define OFF_K  18432
#define OFF_VH (OFF_K + 2*18432)
#define OFF_VL (OFF_VH + 2*18432)
#define OFF_O  (OFF_VL + 2*18432)
#define OFF_RS (OFF_O + 128*66*4)
#define OFF_INV (OFF_RS + 1024)
#define OFF_MB (OFF_INV + 512)
#define FA_SMEM (OFF_MB + 16384)

__global__ __launch_bounds__(512, 1)
void fused_attn(const __nv_bfloat16* __restrict__ Qb, const __nv_bfloat16* __restrict__ Kb,
                const __nv_bfloat16* __restrict__ Vhi, const __nv_bfloat16* __restrict__ Vlo,
                const int* __restrict__ mask,
                __nv_bfloat16* __restrict__ AOhi, __nv_bfloat16* __restrict__ AOlo,
                float* __restrict__ ebuf, int writeE)
{
    extern __shared__ char smem[];
    const uint32_t sb = smem_u32(smem);
    const int tid = threadIdx.x, wid = tid >> 5, lane = tid & 31;
    const int warp_m = wid & 7, warp_n = wid >> 3;
    const int g = lane >> 3, lr = lane & 7;
    const int lr2 = lane >> 2, lc2 = (lane & 3) * 2;
    const int bh = blockIdx.y, b = bh >> 4;
    const int qbase = blockIdx.x * 128;

    const size_t chunk = (size_t)bh * (SS * 64);
    const int* mb = mask + (size_t)b * SS * SS;
    float* eb = ebuf + (size_t)bh * SS * SS;
    const float S64 = 1.0f / 64.0f;

    auto issueK = [&](int jt) {
        const int st = jt & 1;
        const size_t base = chunk + (size_t)jt * (128 * 64);
#pragma unroll
        for (int i = 0; i < 2; i++) {
            int idx = tid + i * 512;
            int r = idx >> 3, cb = (idx & 7) * 16;
            cp_async16(sb + OFF_K + st * 18432 + r * FA_STRIDE + cb,
                       (const char*)(Kb + base) + idx * 16);
        }
        asm volatile("cp.async.commit_group;" ::: "memory");
    };
    auto issueKV = [&](int jt) {
        const int st = jt & 1;
        const size_t base = chunk + (size_t)jt * (128 * 64);
#pragma unroll
        for (int i = 0; i < 2; i++) {
            int idx = tid + i * 512;
            int r = idx >> 3, cb = (idx & 7) * 16;
            cp_async16(sb + OFF_K  + st * 18432 + r * FA_STRIDE + cb, (const char*)(Kb  + base) + idx * 16);
            cp_async16(sb + OFF_VH + st * 18432 + r * FA_STRIDE + cb, (const char*)(Vhi + base) + idx * 16);
            cp_async16(sb + OFF_VL + st * 18432 + r * FA_STRIDE + cb, (const char*)(Vlo + base) + idx * 16);
        }
        asm volatile("cp.async.commit_group;" ::: "memory");
    };

    {
        const size_t qb0 = chunk + (size_t)qbase * 64;
#pragma unroll
        for (int i = 0; i < 2; i++) {
            int idx = tid + i * 512;
            int r = idx >> 3, cb = (idx & 7) * 16;
            cp_async16(sb + OFF_Q + r * FA_STRIDE + cb, (const char*)(Qb + qb0) + idx * 16);
        }
        issueK(0);
    }

    auto computeS = [&](int st, float (*acc_s)[4]) {
#pragma unroll
        for (int j = 0; j < 8; j++)
#pragma unroll
            for (int v = 0; v < 4; v++) acc_s[j][v] = 0.f;
        const uint32_t sKb = sb + OFF_K + st * 18432;
#pragma unroll
        for (int kk = 0; kk < 4; kk++) {
            const uint32_t colb = kk * 32 + ((g >> 1) << 4);
            uint32_t afr[4];
            ld4(afr, sb + OFF_Q + (warp_m * 16 + ((g & 1) << 3) + lr) * FA_STRIDE + colb);
#pragma unroll
            for (int jj = 0; jj < 4; jj++) {
                uint32_t bfr[4];
                ld4(bfr, sKb + (warp_n * 64 + jj * 16 + ((g & 1) << 3) + lr) * FA_STRIDE + colb);
                mma16816(acc_s[2 * jj + 0], afr, bfr[0], bfr[2]);
                mma16816(acc_s[2 * jj + 1], afr, bfr[1], bfr[3]);
            }
        }
    };

    auto mbslot = [&](int jt, int jj) -> uint32_t {
        return sb + OFF_MB + (((jt * 16 + wid)) * 8 + jj) * 16;
    };

    // ================= PASS A =================
    float rs[2] = {0.f, 0.f};
    for (int jt = 0; jt < 8; jt++) {
        const int st = jt & 1;
        if (jt + 1 < 8) {
            issueK(jt + 1);
            asm volatile("cp.async.wait_group 1;" ::: "memory");
        } else {
            asm volatile("cp.async.wait_group 0;" ::: "memory");
        }
        __syncthreads();

        float acc_s[8][4];
        computeS(st, acc_s);

        const int qr = qbase + warp_m * 16 + lr2;
#pragma unroll
        for (int jj = 0; jj < 8; jj++) {
            const int kc = jt * 128 + warp_n * 64 + jj * 8 + lc2;
            int2 m0 = __ldg((const int2*)(mb + (size_t)qr * SS + kc));
            int2 m1 = __ldg((const int2*)(mb + (size_t)(qr + 8) * SS + kc));
            unsigned bl0 = __ballot_sync(0xffffffffu, m0.x != 0);
            unsigned bl1 = __ballot_sync(0xffffffffu, m0.y != 0);
            unsigned bl2 = __ballot_sync(0xffffffffu, m1.x != 0);
            unsigned bl3 = __ballot_sync(0xffffffffu, m1.y != 0);
            if (lane == 0) {
                asm volatile("st.shared.v4.b32 [%0], {%1,%2,%3,%4};"
                             :: "r"(mbslot(jt, jj)),
                                "r"(bl0), "r"(bl1), "r"(bl2), "r"(bl3) : "memory");
            }
            float e0 = m0.x ? __expf(acc_s[jj][0] * S64) : 0.f;
            float e1 = m0.y ? __expf(acc_s[jj][1] * S64) : 0.f;
            float e2 = m1.x ? __expf(acc_s[jj][2] * S64) : 0.f;
            float e3 = m1.y ? __expf(acc_s[jj][3] * S64) : 0.f;
            rs[0] += e0 + e1;
            rs[1] += e2 + e3;
        }
        __syncthreads();
    }

    float* s_rs = (float*)(smem + OFF_RS);
    float* sinv = (float*)(smem + OFF_INV);
#pragma unroll
    for (int h2 = 0; h2 < 2; h2++) {
        float v = rs[h2];
        v += __shfl_xor_sync(0xffffffffu, v, 1);
        v += __shfl_xor_sync(0xffffffffu, v, 2);
        if ((lane & 3) == 0)
            s_rs[warp_n * 128 + warp_m * 16 + lr2 + h2 * 8] = v;
    }
    __syncthreads();
    if (tid < 128) sinv[tid] = 1.0f / (s_rs[tid] + s_rs[128 + tid]);
    __syncthreads();

    const float inva = sinv[warp_m * 16 + lr2];
    const float invb = sinv[warp_m * 16 + lr2 + 8];

    // ================= PASS B =================
    float acc_o[8][4];
#pragma unroll
    for (int j = 0; j < 8; j++)
#pragma unroll
        for (int v = 0; v < 4; v++) acc_o[j][v] = 0.f;

    issueKV(0);
    for (int jt = 0; jt < 8; jt++) {
        const int st = jt & 1;
        if (jt + 1 < 8) {
            issueKV(jt + 1);
            asm volatile("cp.async.wait_group 1;" ::: "memory");
        } else {
            asm volatile("cp.async.wait_group 0;" ::: "memory");
        }
        __syncthreads();

        float acc_s[8][4];
        computeS(st, acc_s);

        const int qr = qbase + warp_m * 16 + lr2;
#pragma unroll
        for (int jj = 0; jj < 8; jj++) {
            const int kc = jt * 128 + warp_n * 64 + jj * 8 + lc2;
            uint32_t w0, w1, w2, w3;
            asm volatile("ld.shared.v4.b32 {%0,%1,%2,%3}, [%4];"
                         : "=r"(w0), "=r"(w1), "=r"(w2), "=r"(w3)
                         : "r"(mbslot(jt, jj)));
            bool b0 = (w0 >> lane) & 1u;
            bool b1 = (w1 >> lane) & 1u;
            bool b2 = (w2 >> lane) & 1u;
            bool b3 = (w3 >> lane) & 1u;
            float e0 = b0 ? __expf(acc_s[jj][0] * S64) * inva : 0.f;
            float e1 = b1 ? __expf(acc_s[jj][1] * S64) * inva : 0.f;
            float e2 = b2 ? __expf(acc_s[jj][2] * S64) * invb : 0.f;
            float e3 = b3 ? __expf(acc_s[jj][3] * S64) * invb : 0.f;
            acc_s[jj][0] = e0; acc_s[jj][1] = e1;
            acc_s[jj][2] = e2; acc_s[jj][3] = e3;
            if (writeE) {
                *(float2*)(eb + (size_t)qr * SS + kc) = make_float2(e0, e1);
                *(float2*)(eb + (size_t)(qr + 8) * SS + kc) = make_float2(e2, e3);
            }
        }

        const uint32_t sVh = sb + OFF_VH + st * 18432;
        const uint32_t sVl = sb + OFF_VL + st * 18432;
#pragma unroll
        for (int u = 0; u < 4; u++) {
            uint32_t vh[4][4], vl[4][4];
#pragma unroll
            for (int jj2 = 0; jj2 < 4; jj2++) {
                const uint32_t addr = (warp_n * 64 + u * 16 + ((g & 1) << 3) + lr) * FA_STRIDE
                                    + jj2 * 32 + ((g >> 1) << 4);
                ld4t(vh[jj2], sVh + addr);
                ld4t(vl[jj2], sVl + addr);
            }
            uint32_t ah[4], al[4];
            packhl(acc_s[2 * u][0],     acc_s[2 * u][1],     ah[0], al[0]);
            packhl(acc_s[2 * u][2],     acc_s[2 * u][3],     ah[1], al[1]);
            packhl(acc_s[2 * u + 1][0], acc_s[2 * u + 1][1], ah[2], al[2]);
            packhl(acc_s[2 * u + 1][2], acc_s[2 * u + 1][3], ah[3], al[3]);
#pragma unroll
            for (int jj2 = 0; jj2 < 4; jj2++) {
                mma16816(acc_o[2 * jj2 + 0], ah, vh[jj2][0], vh[jj2][1]);
                mma16816(acc_o[2 * jj2 + 0], al, vh[jj2][0], vh[jj2][1]);
                mma16816(acc_o[2 * jj2 + 0], ah, vl[jj2][0], vl[jj2][1]);
                mma16816(acc_o[2 * jj2 + 1], ah, vh[jj2][2], vh[jj2][3]);
                mma16816(acc_o[2 * jj2 + 1], al, vh[jj2][2], vh[jj2][3]);
                mma16816(acc_o[2 * jj2 + 1], ah, vl[jj2][2], vl[jj2][3]);
            }
        }
        __syncthreads();
    }

    // ---- O cross-warp reduce + store ----
    float* so = (float*)(smem + OFF_O);
    if (warp_n == 1) {
        int r = warp_m * 16 + lr2;
#pragma unroll
        for (int jj = 0; jj < 8; jj++) {
            int c = jj * 8 + lc2;
            *(float2*)&so[r * 66 + c] = make_float2(acc_o[jj][0], acc_o[jj][1]);
            *(float2*)&so[(r + 8) * 66 + c] = make_float2(acc_o[jj][2], acc_o[jj][3]);
        }
    }
    __syncthreads();
    if (warp_n == 0) {
        int r = warp_m * 16 + lr2;
        size_t row0 = chunk + (size_t)(qbase + r) * 64;
        size_t row1 = chunk + (size_t)(qbase + r + 8) * 64;
#pragma unroll
        for (int jj = 0; jj < 8; jj++) {
            int c = jj * 8 + lc2;
            float o0 = acc_o[jj][0] + so[r * 66 + c];
            float o1 = acc_o[jj][1] + so[r * 66 + c + 1];
            float o2 = acc_o[jj][2] + so[(r + 8) * 66 + c];
            float o3 = acc_o[jj][3] + so[(r + 8) * 66 + c + 1];
            __nv_bfloat16 h0 = __float2bfloat16(o0), h1 = __float2bfloat16(o1);
            __nv_bfloat16 h2 = __float2bfloat16(o2), h3 = __float2bfloat16(o3);
            *(uint32_t*)(AOhi + row0 + c) = packbf2(h0, h1);
            *(uint32_t*)(AOhi + row1 + c) = packbf2(h2, h3);
            *(uint32_t*)(AOlo + row0 + c) =
                packbf2(__float2bfloat16(o0 - __bfloat162float(h0)),
                        __float2bfloat16(o1 - __bfloat162float(h1)));
            *(uint32_t*)(AOlo + row1 + c) =
                packbf2(__float2bfloat16(o2 - __bfloat162float(h2)),
                        __float2bfloat16(o3 - __bfloat162float(h3)));
        }
    }
}

// ---------------------------------------------------------------------------
extern "C" void kernel_launch(void* const* d_in, const int* in_sizes, int n_in,
                              void* d_out, int out_size)
{
    const float* query = (const float*)d_in[0];
    const float* keyy  = (const float*)d_in[1];
    const float* value = (const float*)d_in[2];
    const int*   mask  = (const int*)  d_in[3];
    const float* Wq = (const float*)d_in[4];
    const float* bq = (const float*)d_in[5];
    const float* Wk = (const float*)d_in[6];
    const float* bk = (const float*)d_in[7];
    const float* Wv = (const float*)d_in[8];
    const float* bv = (const float*)d_in[9];
    const float* Wo = (const float*)d_in[10];
    const float* bo = (const float*)d_in[11];
    float* out = (float*)d_out;

    void *pattn, *pah, *pal, *pbh, *pbl, *pqb, *pkb, *pvh, *pvl, *paoh, *paol;
    cudaGetSymbolAddress(&pattn, g_attn);
    cudaGetSymbolAddress(&pah, g_Ahi);
    cudaGetSymbolAddress(&pal, g_Alo);
    cudaGetSymbolAddress(&pbh, g_Bhi);
    cudaGetSymbolAddress(&pbl, g_Blo);
    cudaGetSymbolAddress(&pqb, g_Qb);
    cudaGetSymbolAddress(&pkb, g_Kb);
    cudaGetSymbolAddress(&pvh, g_Vhi);
    cudaGetSymbolAddress(&pvl, g_Vlo);
    cudaGetSymbolAddress(&paoh, g_AOhi);
    cudaGetSymbolAddress(&paol, g_AOlo);

    __nv_bfloat16* Ahi = (__nv_bfloat16*)pah;
    __nv_bfloat16* Alo = (__nv_bfloat16*)pal;
    __nv_bfloat16* Bhi = (__nv_bfloat16*)pbh;
    __nv_bfloat16* Blo = (__nv_bfloat16*)pbl;
    __nv_bfloat16* Qb  = (__nv_bfloat16*)pqb;
    __nv_bfloat16* Kb  = (__nv_bfloat16*)pkb;
    __nv_bfloat16* Vhi = (__nv_bfloat16*)pvh;
    __nv_bfloat16* Vlo = (__nv_bfloat16*)pvl;
    __nv_bfloat16* AOhi = (__nv_bfloat16*)paoh;
    __nv_bfloat16* AOlo = (__nv_bfloat16*)paol;

    const long long OUT_ELEMS  = (long long)BB * SS * DMM;
    const long long ATTN_ELEMS = (long long)NBH * SS * SS;
    int writeE = ((long long)out_size >= OUT_ELEMS + ATTN_ELEMS) ? 1 : 0;
    float* attnbuf = writeE ? (out + OUT_ELEMS) : (float*)pattn;

    static int smem_set = 0;
    if (!smem_set) {
        cudaFuncSetAttribute(fused_attn, cudaFuncAttributeMaxDynamicSharedMemorySize, FA_SMEM);
        cudaFuncSetAttribute(gemm3x, cudaFuncAttributeMaxDynamicSharedMemorySize, G_SMEM);
        smem_set = 1;
    }

    const int n4 = MROWS * DMM / 4;
    dim3 thr(256);

    // split all A inputs (Q/K/V) in one launch
    asplit3<<<dim3(n4 / 256, 3), thr>>>(query, keyy, value, Ahi, Alo);

    // split all 4 weights in one launch
    W4 ws;
    ws.W[0] = Wq; ws.W[1] = Wk; ws.W[2] = Wv; ws.W[3] = Wo;
    wsplit<<<dim3(32, 32, 4), thr>>>(ws, Bhi, Blo);

    // Q/K/V projections (Q,K: 1 segment — outputs rounded to bf16 and error-
    // compressed through exp; V: 3 segments, feeds output linearly)
    G3B bq3;
    for (int z = 0; z < 3; z++) {
        bq3.Ahi[z] = Ahi + (size_t)z * APLANE;
        bq3.Alo[z] = Alo + (size_t)z * APLANE;
        bq3.Bhi[z] = Bhi + (size_t)z * WPLANE;
        bq3.Blo[z] = Blo + (size_t)z * WPLANE;
        bq3.C[z] = nullptr;
    }
    bq3.bias[0] = bq; bq3.bias[1] = bk; bq3.bias[2] = bv;
    bq3.Chi[0] = Qb;  bq3.Chi[1] = Kb;  bq3.Chi[2] = Vhi;
    bq3.Clo[0] = nullptr; bq3.Clo[1] = nullptr; bq3.Clo[2] = Vlo;
    bq3.nseg[0] = 1; bq3.nseg[1] = 1; bq3.nseg[2] = 3;
    gemm3x<<<dim3(DMM / 128, MROWS / 128, 3), thr, G_SMEM>>>(bq3, MROWS, DMM, DMM);

    // fused attention (512 threads) -> AOhi/AOlo + normalized attn
    fused_attn<<<dim3(SS / 128, NBH), dim3(512), FA_SMEM>>>(
        Qb, Kb, Vhi, Vlo, mask, AOhi, AOlo, attnbuf, writeE);

    // out = AO @ Wo + bo  (fp32, full 3 segments — output-linear path)
    G3B bo3;
    bo3.Ahi[0] = AOhi; bo3.Alo[0] = AOlo;
    bo3.Bhi[0] = Bhi + 3 * WPLANE; bo3.Blo[0] = Blo + 3 * WPLANE;
    bo3.bias[0] = bo; bo3.C[0] = out; bo3.Chi[0] = nullptr; bo3.Clo[0] = nullptr;
    bo3.nseg[0] = 3;
    for (int z = 1; z < 3; z++) {
        bo3.Ahi[z] = nullptr; bo3.Alo[z] = nullptr; bo3.Bhi[z] = nullptr;
        bo3.Blo[z] = nullptr; bo3.bias[z] = nullptr; bo3.C[z] = nullptr;
        bo3.Chi[z] = nullptr; bo3.Clo[z] = nullptr; bo3.nseg[z] = 3;
    }
    gemm3x<<<dim3(DMM / 128, MROWS / 128, 1), thr, G_SMEM>>>(bo3, MROWS, DMM, DMM);
}